// round 17
// baseline (speedup 1.0000x reference)
#include <cuda_runtime.h>
#include <cuda_fp16.h>
#include <cstdint>

// Problem constants (fixed by the reference config)
#define SEQ   512
#define BATCH 64
#define NN    1024
#define SIN   64
#define NWARP 8
#define ROW2  (NN/4)       // 256 uint2 (4 halves each) per weight row
#define ZOFF2 (NN*(NN/4))  // uint2 offset of the implicit zero row (bss-zeroed)
#define IDS_ELEMS ((size_t)SEQ * BATCH * SIN)
#define CNT_ELEMS ((size_t)SEQ * BATCH * 2)

// Transposed fp16 weights + one trailing zero row each (zero-initialized bss).
__device__ __align__(16) __half g_W1H[NN * NN + NN];
__device__ __align__(16) __half g_W2H[NN * NN + NN];
// Per-batch "crossing happened" flags; cleared by transpose_both, set by
// phase A, consumed by the fixup kernel. Deterministic across graph replays.
__device__ unsigned g_flags[BATCH];

// ---------------------------------------------------------------------------
// Tiled transpose+convert of both 1024x1024 fp32 matrices to fp16.
// Block (0,0,0) also clears the per-batch fixup flags.
// ---------------------------------------------------------------------------
__global__ void transpose_both(const float* __restrict__ W1in,
                               const float* __restrict__ W2in) {
    __shared__ float tile[32][33];
    const float* in  = blockIdx.z ? W2in : W1in;
    __half*      out = blockIdx.z ? g_W2H : g_W1H;
    int bx = blockIdx.x * 32, by = blockIdx.y * 32;
    int tx = threadIdx.x, ty = threadIdx.y;
    if (blockIdx.x == 0 && blockIdx.y == 0 && blockIdx.z == 0) {
        int flat = ty * 32 + tx;
        if (flat < BATCH) g_flags[flat] = 0u;
    }
#pragma unroll
    for (int j = 0; j < 32; j += 8)
        tile[ty + j][tx] = in[(size_t)(by + ty + j) * NN + (bx + tx)];
    __syncthreads();
#pragma unroll
    for (int j = 0; j < 32; j += 8)
        out[(size_t)(bx + ty + j) * NN + (by + tx)] = __float2half(tile[tx][ty + j]);
}

// ---------------------------------------------------------------------------
// Phase A: decoupled per-neuron LIF assuming no threshold crossings, with the
// W1 gather software-pipelined ACROSS timesteps: the 16 LDG.64 for step t+1
// are issued right after step t's accumulation, so the L2 round trip overlaps
// the barrier + v-update + next step's front instead of the critical path.
// ids are prefetched two steps ahead (triple-buffered s_off).
// One CTA = (batch b, slice of 256 neurons); group g of 64 threads owns the
// contiguous row block [16g, 16g+16) — only groups g < ceil(num/16) work.
// Group 0 owns v1, group 1 owns v2 (pure decay), group 3 runs the ids
// pipeline; groups 2/3 of slice 0 emit the closed-form ids/cnt outputs.
// Any crossing sets g_flags[b]; the fixup kernel recomputes that b exactly.
// ---------------------------------------------------------------------------
__global__ __launch_bounds__(256, 2)
void lif_phaseA(const float* __restrict__ decay1, const float* __restrict__ decay2,
                const float* __restrict__ th1,    const float* __restrict__ th2,
                const float* __restrict__ v1init, const float* __restrict__ v2init,
                const int* __restrict__ spk_ids,  const int* __restrict__ spk_num,
                float* __restrict__ out)
{
    const int b     = blockIdx.x >> 2;
    const int slice = blockIdx.x & 3;
    const int tid   = threadIdx.x;
    const int g     = tid >> 6;          // spike group 0..3 (2 warps each)
    const int col   = tid & 63;          // uint2 column within the 256-neuron slice
    const int cix   = slice * 64 + col;  // uint2 index within a row

    float* out_ids1 = out;
    float* out_ids2 = out + IDS_ELEMS;
    float* out_cnt1 = out + 2 * IDS_ELEMS;
    float* out_cnt2 = out_cnt1 + CNT_ELEMS;
    float* out_st1  = out_cnt2 + CNT_ELEMS;
    float* out_st2  = out_st1 + (size_t)SEQ * BATCH * NN;

    __shared__ int    s_off[3][SIN];     // triple-buffered pre-scaled row offsets
    __shared__ int    s_num[3];
    __shared__ float4 s_part[2][3][64];  // partial sums from groups 1..3

    // Per-group state (uniform branches: groups are whole warps)
    float4 v1, d1, od1, h1, t1;
    float4 v2, d2, h2, t2v;
    if (g == 0) {
        v1 = ((const float4*)v1init)[b * (NN/4) + cix];
        d1 = ((const float4*)decay1)[cix];
        t1 = ((const float4*)th1)[cix];
        od1 = make_float4(1.f - d1.x, 1.f - d1.y, 1.f - d1.z, 1.f - d1.w);
        h1 = make_float4(0.9f*t1.x, 0.9f*t1.y, 0.9f*t1.z, 0.9f*t1.w);
    } else if (g == 1) {
        v2 = ((const float4*)v2init)[b * (NN/4) + cix];
        d2 = ((const float4*)decay2)[cix];
        t2v = ((const float4*)th2)[cix];
        h2 = make_float4(0.9f*t2v.x, 0.9f*t2v.y, 0.9f*t2v.z, 0.9f*t2v.w);
    }
    const float fcol = (float)col;       // closed-form id value

    // ---- prologue: stage ids(0) and ids(1) ----
    if (tid < SIN) {
        int num0 = spk_num[b];
        int id0  = spk_ids[(size_t)b * SIN + tid];
        s_off[0][tid] = (tid < num0) ? id0 * ROW2 : ZOFF2;
        int num1 = spk_num[BATCH + b];
        int id1  = spk_ids[(size_t)(BATCH + b) * SIN + tid];
        s_off[1][tid] = (tid < num1) ? id1 * ROW2 : ZOFF2;
        if (tid == 0) { s_num[0] = num0; s_num[1] = num1; }
    }
    __syncthreads();

    const uint2* __restrict__ W1u = (const uint2*)g_W1H;
    unsigned flag = 0;

    // ---- issue gather for step 0 ----
    uint2 w[16];
    {
        int nact0 = (s_num[0] + 15) >> 4;
        if (g < nact0) {
#pragma unroll
            for (int k = 0; k < 16; k++)
                w[k] = W1u[s_off[0][g * 16 + k] + cix];
        }
    }

    for (int t = 0; t < SEQ; t++) {
        const int bufc  = t % 3;
        const int bufn  = (t + 1) % 3;
        const int bufn2 = (t + 2) % 3;
        const int pb    = t & 1;             // s_part parity
        const size_t tbIdx = (size_t)t * BATCH + b;

        // group 3 prefetches ids(t+2) (latency hidden under the step)
        int nid = 0, nnum = 0;
        if (g == 3) {
            int tn = (t + 2 < SEQ) ? t + 2 : SEQ - 1;
            nnum = spk_num[tn * BATCH + b];
            nid  = spk_ids[((size_t)tn * BATCH + b) * SIN + col];
        }

        // ---- accumulate step t's already-loaded rows ----
        const int nact = (s_num[bufc] + 15) >> 4;
        float4 acc = make_float4(0.f, 0.f, 0.f, 0.f);
        if (g < nact) {
            float4 p0 = make_float4(0.f,0.f,0.f,0.f), p1 = p0, p2 = p0, p3 = p0;
#pragma unroll
            for (int k = 0; k < 16; k += 4) {
                float2 a, bb;
                a = __half22float2(*(__half2*)&w[k+0].x); bb = __half22float2(*(__half2*)&w[k+0].y);
                p0.x += a.x; p0.y += a.y; p0.z += bb.x; p0.w += bb.y;
                a = __half22float2(*(__half2*)&w[k+1].x); bb = __half22float2(*(__half2*)&w[k+1].y);
                p1.x += a.x; p1.y += a.y; p1.z += bb.x; p1.w += bb.y;
                a = __half22float2(*(__half2*)&w[k+2].x); bb = __half22float2(*(__half2*)&w[k+2].y);
                p2.x += a.x; p2.y += a.y; p2.z += bb.x; p2.w += bb.y;
                a = __half22float2(*(__half2*)&w[k+3].x); bb = __half22float2(*(__half2*)&w[k+3].y);
                p3.x += a.x; p3.y += a.y; p3.z += bb.x; p3.w += bb.y;
            }
            acc = make_float4((p0.x + p1.x) + (p2.x + p3.x),
                              (p0.y + p1.y) + (p2.y + p3.y),
                              (p0.z + p1.z) + (p2.z + p3.z),
                              (p0.w + p1.w) + (p2.w + p3.w));
            if (g != 0) s_part[pb][g-1][col] = acc;
        }

        // ---- issue gather loads for step t+1 (overlaps barrier + update) ----
        {
            int nactn = (s_num[bufn] + 15) >> 4;
            if (g < nactn) {
#pragma unroll
                for (int k = 0; k < 16; k++)
                    w[k] = W1u[s_off[bufn][g * 16 + k] + cix];
            }
        }

        // ---- closed-form ids/cnt outputs (slice 0 only; idle-group work) ----
        if (slice == 0) {
            if (g == 2) {
                __stcs(&out_ids1[tbIdx * SIN + col], fcol);
                if (col < 2) __stcs(&out_cnt1[tbIdx * 2 + col], 0.0f);
            } else if (g == 3) {
                __stcs(&out_ids2[tbIdx * SIN + col], fcol);
                if (col < 2) __stcs(&out_cnt2[tbIdx * 2 + col], 0.0f);
            }
        }

        // commit prefetched ids(t+2)
        if (g == 3) {
            s_off[bufn2][col] = (col < nnum) ? nid * ROW2 : ZOFF2;
            if (col == 0) s_num[bufn2] = nnum;
        }
        __syncthreads();    // the ONLY barrier per step

        if (g == 0) {
#pragma unroll
            for (int j = 0; j < 3; j++) {
                if (j + 1 < nact) {
                    float4 q = s_part[pb][j][col];
                    acc.x += q.x; acc.y += q.y; acc.z += q.z; acc.w += q.w;
                }
            }
            v1.x = d1.x * v1.x + od1.x * acc.x;
            v1.y = d1.y * v1.y + od1.y * acc.y;
            v1.z = d1.z * v1.z + od1.z * acc.z;
            v1.w = d1.w * v1.w + od1.w * acc.w;
            if (v1.x > h1.x || v1.y > h1.y || v1.z > h1.z || v1.w > h1.w ||
                v1.x > t1.x || v1.y > t1.y || v1.z > t1.z || v1.w > t1.w) flag = 1;
            __stcs(&((float4*)out_st1)[tbIdx * (NN/4) + cix], v1);
        } else if (g == 1) {
            v2.x = d2.x * v2.x;
            v2.y = d2.y * v2.y;
            v2.z = d2.z * v2.z;
            v2.w = d2.w * v2.w;
            if (v2.x > h2.x || v2.y > h2.y || v2.z > h2.z || v2.w > h2.w ||
                v2.x > t2v.x || v2.y > t2v.y || v2.z > t2v.z || v2.w > t2v.w) flag = 1;
            __stcs(&((float4*)out_st2)[tbIdx * (NN/4) + cix], v2);
        }
    }
    if (flag) atomicOr(&g_flags[b], 1u);
}

// ---------------------------------------------------------------------------
// Gather-accumulate fp16 rows from gmem (fixup path). off[] pre-scaled,
// padded to numPad (multiple of 16) with zero-row offsets.
// ---------------------------------------------------------------------------
__device__ __forceinline__ float4 gather_h2(const uint2* __restrict__ W,
                                            const int* __restrict__ off,
                                            int numPad, int tid)
{
    float4 acc = make_float4(0.f, 0.f, 0.f, 0.f);
    for (int cc = 0; cc < numPad; cc += 16) {
        uint2 w[16];
#pragma unroll
        for (int j = 0; j < 16; j++)
            w[j] = W[off[cc + j] + tid];
        float4 p0 = make_float4(0.f,0.f,0.f,0.f), p1 = p0, p2 = p0, p3 = p0;
#pragma unroll
        for (int j = 0; j < 16; j += 4) {
            float2 a0 = __half22float2(*reinterpret_cast<__half2*>(&w[j+0].x));
            float2 b0 = __half22float2(*reinterpret_cast<__half2*>(&w[j+0].y));
            p0.x += a0.x; p0.y += a0.y; p0.z += b0.x; p0.w += b0.y;
            float2 a1 = __half22float2(*reinterpret_cast<__half2*>(&w[j+1].x));
            float2 b1 = __half22float2(*reinterpret_cast<__half2*>(&w[j+1].y));
            p1.x += a1.x; p1.y += a1.y; p1.z += b1.x; p1.w += b1.y;
            float2 a2 = __half22float2(*reinterpret_cast<__half2*>(&w[j+2].x));
            float2 b2 = __half22float2(*reinterpret_cast<__half2*>(&w[j+2].y));
            p2.x += a2.x; p2.y += a2.y; p2.z += b2.x; p2.w += b2.y;
            float2 a3 = __half22float2(*reinterpret_cast<__half2*>(&w[j+3].x));
            float2 b3 = __half22float2(*reinterpret_cast<__half2*>(&w[j+3].y));
            p3.x += a3.x; p3.y += a3.y; p3.z += b3.x; p3.w += b3.y;
        }
        acc.x += (p0.x + p1.x) + (p2.x + p3.x);
        acc.y += (p0.y + p1.y) + (p2.y + p3.y);
        acc.z += (p0.z + p1.z) + (p2.z + p3.z);
        acc.w += (p0.w + p1.w) + (p2.w + p3.w);
    }
    return acc;
}

// ---------------------------------------------------------------------------
// Fixup: exact coupled recomputation of one batch element, run only when
// phase A flagged a threshold crossing for it. Overwrites ALL outputs of b.
// ---------------------------------------------------------------------------
__global__ __launch_bounds__(256, 1)
void lif_fixup(const float* __restrict__ decay1, const float* __restrict__ decay2,
               const float* __restrict__ th1,    const float* __restrict__ th2,
               const float* __restrict__ v1init, const float* __restrict__ v2init,
               const int* __restrict__ spk_ids,  const int* __restrict__ spk_num,
               float* __restrict__ out)
{
    const int b = blockIdx.x;
    if (g_flags[b] == 0) return;     // common case: nothing to fix

    const int tid  = threadIdx.x;
    const int lane = tid & 31;
    const int warp = tid >> 5;

    float* out_ids1 = out;
    float* out_ids2 = out + IDS_ELEMS;
    float* out_cnt1 = out + 2 * IDS_ELEMS;
    float* out_cnt2 = out_cnt1 + CNT_ELEMS;
    float* out_st1  = out_cnt2 + CNT_ELEMS;
    float* out_st2  = out_st1 + (size_t)SEQ * BATCH * NN;

    float4 v1 = ((const float4*)v1init)[b * (NN/4) + tid];
    float4 v2 = ((const float4*)v2init)[b * (NN/4) + tid];
    const float4 d1 = ((const float4*)decay1)[tid];
    const float4 d2 = ((const float4*)decay2)[tid];
    const float4 t1 = ((const float4*)th1)[tid];
    const float4 t2 = ((const float4*)th2)[tid];
    const float4 od1 = make_float4(1.f - d1.x, 1.f - d1.y, 1.f - d1.z, 1.f - d1.w);
    const float4 od2 = make_float4(1.f - d2.x, 1.f - d2.y, 1.f - d2.z, 1.f - d2.w);
    const float4 h1 = make_float4(0.9f*t1.x, 0.9f*t1.y, 0.9f*t1.z, 0.9f*t1.w);
    const float4 h2 = make_float4(0.9f*t2.x, 0.9f*t2.y, 0.9f*t2.z, 0.9f*t2.w);

    __shared__ int s_ids[SIN];
    __shared__ int s_num;
    __shared__ int s_spk[NN];
    __shared__ int s_spkoff[NN + 16];
    __shared__ int s_ns[SIN];
    __shared__ int s_spk2[SIN];
    __shared__ int s_ns2[SIN];
    __shared__ int s_wsum[NWARP];
    __shared__ int s_tot;

    const uint2* __restrict__ W1 = (const uint2*)g_W1H;
    const uint2* __restrict__ W2 = (const uint2*)g_W2H;

    for (int t = 0; t < SEQ; t++) {
        const size_t tbIdx = (size_t)t * BATCH + b;
        if (tid < SIN) {
            int num = spk_num[t * BATCH + b];
            int id  = spk_ids[tbIdx * SIN + tid];
            s_ids[tid] = (tid < num) ? id * ROW2 : ZOFF2;
            if (tid == 0) s_num = num;
        }
        __syncthreads();

        // layer 1
        const int num = s_num;
        float4 acc = gather_h2(W1, s_ids, (num + 15) & ~15, tid);
        v1.x = d1.x * v1.x + od1.x * acc.x;
        v1.y = d1.y * v1.y + od1.y * acc.y;
        v1.z = d1.z * v1.z + od1.z * acc.z;
        v1.w = d1.w * v1.w + od1.w * acc.w;
        const bool p0 = v1.x > t1.x, p1 = v1.y > t1.y,
                   p2 = v1.z > t1.z, p3 = v1.w > t1.w;
        int c  = (int)p0 + (int)p1 + (int)p2 + (int)p3;
        int c2 = (int)(v1.x > h1.x) + (int)(v1.y > h1.y)
               + (int)(v1.z > h1.z) + (int)(v1.w > h1.w);
        int packed = c | (c2 << 16);
        int incl = packed;
#pragma unroll
        for (int o = 1; o < 32; o <<= 1) {
            int y = __shfl_up_sync(0xffffffffu, incl, o);
            if (lane >= o) incl += y;
        }
        if (lane == 31) s_wsum[warp] = incl;
        __syncthreads();
        if (warp == 0) {
            int v = (lane < NWARP) ? s_wsum[lane] : 0;
            int e = v;
#pragma unroll
            for (int o = 1; o < NWARP; o <<= 1) {
                int y = __shfl_up_sync(0xffffffffu, e, o);
                if (lane >= o) e += y;
            }
            if (lane < NWARP) s_wsum[lane] = e - v;
            if (lane == NWARP - 1) s_tot = e;
        }
        __syncthreads();
        int gp          = (s_wsum[warp] + (incl - packed)) & 0xffff;
        const int c1tot = s_tot & 0xffff;
        const int c2tot = s_tot >> 16;

        const int n0 = tid * 4;
        const bool pr[4] = {p0, p1, p2, p3};
#pragma unroll
        for (int k = 0; k < 4; k++) {
            int id = n0 + k;
            if (pr[k]) { s_spk[gp] = id; s_spkoff[gp] = id * ROW2; gp++; }
            else       { int np = id - gp; if (np < SIN) s_ns[np] = id; }
        }
        if (tid < 16) s_spkoff[c1tot + tid] = ZOFF2;
        if (p0) v1.x = 0.0f;
        if (p1) v1.y = 0.0f;
        if (p2) v1.z = 0.0f;
        if (p3) v1.w = 0.0f;
        ((float4*)out_st1)[tbIdx * (NN/4) + tid] = v1;
        __syncthreads();

        if (tid < SIN) {
            int id = (tid < c1tot) ? s_spk[tid] : s_ns[tid - c1tot];
            out_ids1[tbIdx * SIN + tid] = (float)id;
        }
        if (tid < 2)
            out_cnt1[tbIdx * 2 + tid] = (float)(tid == 0 ? c1tot : c2tot);

        // layer 2
        float4 acc2 = gather_h2(W2, s_spkoff, (c1tot + 15) & ~15, tid);
        v2.x = d2.x * v2.x + od2.x * acc2.x;
        v2.y = d2.y * v2.y + od2.y * acc2.y;
        v2.z = d2.z * v2.z + od2.z * acc2.z;
        v2.w = d2.w * v2.w + od2.w * acc2.w;
        const bool q0 = v2.x > t2.x, q1 = v2.y > t2.y,
                   q2 = v2.z > t2.z, q3 = v2.w > t2.w;
        c  = (int)q0 + (int)q1 + (int)q2 + (int)q3;
        c2 = (int)(v2.x > h2.x) + (int)(v2.y > h2.y)
           + (int)(v2.z > h2.z) + (int)(v2.w > h2.w);
        packed = c | (c2 << 16);
        incl = packed;
#pragma unroll
        for (int o = 1; o < 32; o <<= 1) {
            int y = __shfl_up_sync(0xffffffffu, incl, o);
            if (lane >= o) incl += y;
        }
        if (lane == 31) s_wsum[warp] = incl;
        __syncthreads();
        if (warp == 0) {
            int v = (lane < NWARP) ? s_wsum[lane] : 0;
            int e = v;
#pragma unroll
            for (int o = 1; o < NWARP; o <<= 1) {
                int y = __shfl_up_sync(0xffffffffu, e, o);
                if (lane >= o) e += y;
            }
            if (lane < NWARP) s_wsum[lane] = e - v;
            if (lane == NWARP - 1) s_tot = e;
        }
        __syncthreads();
        int gq           = (s_wsum[warp] + (incl - packed)) & 0xffff;
        const int c1tot2 = s_tot & 0xffff;
        const int c2tot2 = s_tot >> 16;

        const bool qr[4] = {q0, q1, q2, q3};
#pragma unroll
        for (int k = 0; k < 4; k++) {
            int id = n0 + k;
            if (qr[k]) { if (gq < SIN) s_spk2[gq] = id; gq++; }
            else       { int np = id - gq; if (np < SIN) s_ns2[np] = id; }
        }
        if (q0) v2.x = 0.0f;
        if (q1) v2.y = 0.0f;
        if (q2) v2.z = 0.0f;
        if (q3) v2.w = 0.0f;
        ((float4*)out_st2)[tbIdx * (NN/4) + tid] = v2;
        __syncthreads();

        if (tid < SIN) {
            int id = (tid < c1tot2) ? s_spk2[tid] : s_ns2[tid - c1tot2];
            out_ids2[tbIdx * SIN + tid] = (float)id;
        }
        if (tid < 2)
            out_cnt2[tbIdx * 2 + tid] = (float)(tid == 0 ? c1tot2 : c2tot2);
        __syncthreads();   // s_ids rewrite next step
    }
}

// ---------------------------------------------------------------------------
extern "C" void kernel_launch(void* const* d_in, const int* in_sizes, int n_in,
                              void* d_out, int out_size) {
    const float* W1     = (const float*)d_in[0];
    const float* W2     = (const float*)d_in[1];
    const float* decay1 = (const float*)d_in[2];
    const float* decay2 = (const float*)d_in[3];
    const float* th1    = (const float*)d_in[4];
    const float* th2    = (const float*)d_in[5];
    const float* v1init = (const float*)d_in[6];
    const float* v2init = (const float*)d_in[7];
    const int*   spkids = (const int*)d_in[8];
    const int*   spknum = (const int*)d_in[9];
    float* out = (float*)d_out;

    dim3 tb(32, 8), tg(32, 32, 2);
    transpose_both<<<tg, tb>>>(W1, W2);
    lif_phaseA<<<BATCH * 4, 256>>>(decay1, decay2, th1, th2,
                                   v1init, v2init, spkids, spknum, out);
    lif_fixup<<<BATCH, 256>>>(decay1, decay2, th1, th2,
                              v1init, v2init, spkids, spknum, out);
}